// round 5
// baseline (speedup 1.0000x reference)
#include <cuda_runtime.h>

#define NB    32
#define NC    2
#define PP    262144             // H*W
#define BINS  1024
#define ROWS  (NC * NB)          // 64 rows, row = cc*NB + n
#define BPS   16                 // blocks per sample -> 512 blocks
#define HT    512                // hist threads per block
#define NW    (HT / 32)
#define PXB   (PP / BPS)         // 16384 pixels per block
#define ITERS (PXB / (HT * 4))   // 8 iterations of 4 pixels
#define ST    512                // scan threads
#define SEG   (BINS / ST)        // 2 bins per scan thread
#define SNW   (ST / 32)

// Scratch (static device globals, zero-initialized at load; reset each call)
__device__ unsigned int g_part[(size_t)NB * BPS * NC * BINS]; // per-block partial hists (overwritten)
__device__ int          g_npred[ROWS];
__device__ int          g_done;
__device__ float        g_wrow[ROWS];
__device__ unsigned int g_valid[ROWS];

// ---------------------------------------------------------------- histogram
// grid = (BPS, NB). Private smem hist, plain STG flush to g_part (no atomics).
__global__ void __launch_bounds__(HT) k_hist(const float* __restrict__ x,
                                             const void*  __restrict__ tgt) {
  __shared__ unsigned int sh[2 * BINS];   // 8 KB: [0,BINS)=c0, [BINS,2B)=c1
  const int n   = blockIdx.y;
  const int b   = blockIdx.x;
  const int tid = threadIdx.x;

  for (int i = tid; i < 2 * BINS; i += HT) sh[i] = 0u;

  // Detect targets dtype: if int32, odd 32-bit words carry real data -> some
  // nonzero. If int64 (values 0/1), odd words are all zero. Doubles as barrier.
  const int* t32 = (const int*)tgt;
  int probe = t32[2 * tid + 1];
  bool is32 = __syncthreads_or(probe != 0);

  const int base = b * PXB;
  int c0 = 0, c1 = 0;
#pragma unroll 4
  for (int it = 0; it < ITERS; it++) {
    const int p = base + (it * HT + tid) * 4;

    long long tv[4];
    if (is32) {
      int4 q = *(const int4*)(t32 + (size_t)n * PP + p);
      tv[0] = q.x; tv[1] = q.y; tv[2] = q.z; tv[3] = q.w;
    } else {
      longlong4 q = *(const longlong4*)((const long long*)tgt + (size_t)n * PP + p);
      tv[0] = q.x; tv[1] = q.y; tv[2] = q.z; tv[3] = q.w;
    }
    float4 v0 = *(const float4*)(x + ((size_t)n * NC + 0) * PP + p);
    float4 v1 = *(const float4*)(x + ((size_t)n * NC + 1) * PP + p);
    float xs0[4] = {v0.x, v0.y, v0.z, v0.w};
    float xs1[4] = {v1.x, v1.y, v1.z, v1.w};

#pragma unroll
    for (int k = 0; k < 4; k++) {
      bool  m0 = (tv[k] == 0);            // class-0 mask; class-1 mask = !m0
      float a0 = xs0[k], a1 = xs1[k];
      c0 += (a0 > 0.25f);
      c1 += (a1 > 0.25f);
      float d0 = m0 ? (1.0f - a0) : a0;   // |mask - x|
      float d1 = m0 ? a1 : (1.0f - a1);
      unsigned int b0 = min((unsigned int)(d0 * (float)BINS), (unsigned int)(BINS - 1));
      unsigned int b1 = min((unsigned int)(d1 * (float)BINS), (unsigned int)(BINS - 1));
      atomicAdd(&sh[b0],        m0 ? 0x10000u : 1u);
      atomicAdd(&sh[BINS + b1], m0 ? 1u : 0x10000u);
    }
  }
  __syncthreads();

  // flush: plain vectorized stores to this block's private slot
  uint4* __restrict__ dst =
      (uint4*)(g_part + ((size_t)(n * BPS + b) * NC) * BINS);
  const uint4* __restrict__ src = (const uint4*)sh;
#pragma unroll
  for (int i = tid; i < (2 * BINS) / 4; i += HT) dst[i] = src[i];

  // npred block reduce + 2 global atomics
  int lane = tid & 31, w = tid >> 5;
#pragma unroll
  for (int off = 16; off; off >>= 1) {
    c0 += __shfl_down_sync(0xffffffffu, c0, off);
    c1 += __shfl_down_sync(0xffffffffu, c1, off);
  }
  __shared__ int s0[NW], s1[NW];
  if (lane == 0) { s0[w] = c0; s1[w] = c1; }
  __syncthreads();
  if (tid == 0) {
    int a = 0, bb = 0;
#pragma unroll
    for (int i = 0; i < NW; i++) { a += s0[i]; bb += s1[i]; }
    atomicAdd(&g_npred[n], a);
    atomicAdd(&g_npred[NB + n], bb);
  }
}

// ---------------------------------------------------------------- scan + finalize
// One block per row. Sums BPS partial hists, block-scans, Lovász walk.
// Last-finishing block does the deterministic final reduction with 64 threads.
__global__ void __launch_bounds__(ST) k_scan(const float* __restrict__ cw,
                                             const float* __restrict__ tw,
                                             float* __restrict__ out) {
  const int r    = blockIdx.x;        // row = cc*NB + n
  const int cc   = r >> 5;
  const int n    = r & 31;
  const int t    = threadIdx.x;
  const int lane = t & 31;
  const int w    = t >> 5;

  // thread t owns SEG bins [g, g+SEG); thread 0 owns the HIGHEST bins
  const int g = BINS - SEG - t * SEG;

  // fully unrolled: 16 independent LDG.64 front-batched (MLP 16)
  unsigned int h1[SEG], htot[SEG];
#pragma unroll
  for (int j = 0; j < SEG; j++) { h1[j] = 0u; htot[j] = 0u; }

#pragma unroll
  for (int b = 0; b < BPS; b++) {
    uint2 v = *(const uint2*)(g_part + ((size_t)(n * BPS + b) * NC + cc) * BINS + g);
    unsigned int vv[2] = {v.x, v.y};
#pragma unroll
    for (int j = 0; j < SEG; j++) {
      unsigned int one = vv[j] >> 16;
      h1[j]   += one;
      htot[j] += one + (vv[j] & 0xffffu);
    }
  }

  // segment sums
  unsigned int s1 = 0, st = 0;
#pragma unroll
  for (int j = 0; j < SEG; j++) { s1 += h1[j]; st += htot[j]; }

  // inclusive block scan over packed (s1|st) via warp shuffles
  __shared__ unsigned long long swarp[SNW];
  unsigned long long mine = ((unsigned long long)s1 << 32) | (unsigned long long)st;
  unsigned long long inc = mine;
#pragma unroll
  for (int off = 1; off < 32; off <<= 1) {
    unsigned long long u = __shfl_up_sync(0xffffffffu, inc, off);
    if (lane >= off) inc += u;
  }
  if (lane == 31) swarp[w] = inc;
  __syncthreads();
  if (w == 0) {
    unsigned long long v = (lane < SNW) ? swarp[lane] : 0ull;
#pragma unroll
    for (int off = 1; off < SNW; off <<= 1) {
      unsigned long long u = __shfl_up_sync(0xffffffffu, v, off);
      if (lane >= off) v += u;
    }
    if (lane < SNW) swarp[lane] = v;
  }
  __syncthreads();
  unsigned long long woff = (w == 0) ? 0ull : swarp[w - 1];
  unsigned long long tot  = swarp[SNW - 1];
  unsigned long long excl = woff + inc - mine;

  const unsigned int gts = (unsigned int)(tot >> 32);
  unsigned int K1 = (unsigned int)(excl >> 32);
  unsigned int K  = (unsigned int)(excl & 0xffffffffull);

  float iou_prev = (K == 0)
      ? 0.0f
      : 1.0f - __fdividef((float)(gts - K1), (float)(gts + K - K1));

  // walk the segment high->low:  acc += d_bin * (iou - iou_prev)
  float acc = 0.0f;
#pragma unroll
  for (int j = SEG - 1; j >= 0; j--) {
    if (htot[j]) {
      K1 += h1[j];
      K  += htot[j];
      float iou = 1.0f - __fdividef((float)(gts - K1), (float)(gts + K - K1));
      float d   = ((float)(g + j) + 0.5f) * (1.0f / (float)BINS);
      acc += d * (iou - iou_prev);
      iou_prev = iou;
    }
  }

  // block reduce acc (fixed tree -> deterministic)
  __shared__ float sred[SNW];
#pragma unroll
  for (int off = 16; off; off >>= 1)
    acc += __shfl_down_sync(0xffffffffu, acc, off);
  if (lane == 0) sred[w] = acc;
  __syncthreads();

  __shared__ int slast;
  if (t == 0) {
    float per = 0.0f;
#pragma unroll
    for (int i = 0; i < SNW; i++) per += sred[i];
    int   np    = g_npred[r];
    float cwv   = cw[cc];
    bool  empty = (gts == 0) && (np == 0);
    bool  valid = (cwv != 0.0f) && !empty;
    g_wrow[r]  = valid ? per * tw[n] * cwv : 0.0f;
    g_valid[r] = valid ? 1u : 0u;
    g_npred[r] = 0;                      // reset for next replay
    __threadfence();
    int old = atomicAdd(&g_done, 1);
    slast = (old == ROWS - 1);
  }
  __syncthreads();

  // last-finishing block: parallel deterministic final reduction (64 lanes)
  if (slast) {
    __threadfence();
    float Wv = 0.0f, Vv = 0.0f;
    if (t < ROWS) {
      Wv = __ldcg(&g_wrow[t]);
      Vv = (float)__ldcg(&g_valid[t]);
    }
#pragma unroll
    for (int off = 16; off; off >>= 1) {
      Wv += __shfl_down_sync(0xffffffffu, Wv, off);
      Vv += __shfl_down_sync(0xffffffffu, Vv, off);
    }
    __shared__ float fw[2], fv[2];
    if (lane == 0 && w < 2) { fw[w] = Wv; fv[w] = Vv; }
    __syncthreads();
    if (t == 0) {
      out[0] = (fw[0] + fw[1]) / (float)NB / (fv[0] + fv[1]);
      g_done = 0;                        // reset for next replay
    }
  }
}

// ---------------------------------------------------------------- launch
extern "C" void kernel_launch(void* const* d_in, const int* in_sizes, int n_in,
                              void* d_out, int out_size) {
  const float* x   = (const float*)d_in[0];
  const void*  tgt = d_in[1];
  const float* cw  = (const float*)d_in[2];
  const float* tw  = (const float*)d_in[3];
  float* out = (float*)d_out;

  dim3 grid(BPS, NB);
  k_hist<<<grid, HT>>>(x, tgt);
  k_scan<<<ROWS, ST>>>(cw, tw, out);
}

// round 6
// speedup vs baseline: 1.3361x; 1.3361x over previous
#include <cuda_runtime.h>

#define NB    32
#define NC    2
#define PP    262144             // H*W
#define BINS  2048
#define ROWS  (NC * NB)          // 64 rows, row = cc*NB + n
#define BPS   16                 // blocks per sample -> 512 blocks
#define HT    512                // hist threads per block
#define NW    (HT / 32)
#define PXB   (PP / BPS)         // 16384 pixels per block
#define ITERS (PXB / (HT * 4))   // 8 iterations of 4 pixels
#define ST    1024               // scan threads
#define SEG   (BINS / ST)        // 2 bins per scan thread
#define SNW   (ST / 32)

// Scratch (static device globals, zero-initialized at load; reset each call)
__device__ unsigned int g_part[(size_t)NB * BPS * NC * BINS]; // per-block partial hists (overwritten)
__device__ int          g_npred[ROWS];
__device__ int          g_done;
__device__ float        g_wrow[ROWS];
__device__ unsigned int g_valid[ROWS];

// ---------------------------------------------------------------- histogram
// grid = (BPS, NB). Private smem hist, plain STG flush to g_part (no atomics).
__global__ void __launch_bounds__(HT) k_hist(const float* __restrict__ x,
                                             const void*  __restrict__ tgt) {
  __shared__ unsigned int sh[2 * BINS];   // 16 KB: [0,BINS)=c0, [BINS,2B)=c1
  const int n   = blockIdx.y;
  const int b   = blockIdx.x;
  const int tid = threadIdx.x;

  for (int i = tid; i < 2 * BINS; i += HT) sh[i] = 0u;

  // Detect targets dtype: if int32, odd 32-bit words carry real data -> some
  // nonzero. If int64 (values 0/1), odd words are all zero. Doubles as barrier.
  const int* t32 = (const int*)tgt;
  int probe = t32[2 * tid + 1];
  bool is32 = __syncthreads_or(probe != 0);

  const int base = b * PXB;
  int c0 = 0, c1 = 0;
#pragma unroll 4
  for (int it = 0; it < ITERS; it++) {
    const int p = base + (it * HT + tid) * 4;

    long long tv[4];
    if (is32) {
      int4 q = *(const int4*)(t32 + (size_t)n * PP + p);
      tv[0] = q.x; tv[1] = q.y; tv[2] = q.z; tv[3] = q.w;
    } else {
      longlong4 q = *(const longlong4*)((const long long*)tgt + (size_t)n * PP + p);
      tv[0] = q.x; tv[1] = q.y; tv[2] = q.z; tv[3] = q.w;
    }
    float4 v0 = *(const float4*)(x + ((size_t)n * NC + 0) * PP + p);
    float4 v1 = *(const float4*)(x + ((size_t)n * NC + 1) * PP + p);
    float xs0[4] = {v0.x, v0.y, v0.z, v0.w};
    float xs1[4] = {v1.x, v1.y, v1.z, v1.w};

#pragma unroll
    for (int k = 0; k < 4; k++) {
      bool  m0 = (tv[k] == 0);            // class-0 mask; class-1 mask = !m0
      float a0 = xs0[k], a1 = xs1[k];
      c0 += (a0 > 0.25f);
      c1 += (a1 > 0.25f);
      float d0 = m0 ? (1.0f - a0) : a0;   // |mask - x|
      float d1 = m0 ? a1 : (1.0f - a1);
      unsigned int b0 = min((unsigned int)(d0 * (float)BINS), (unsigned int)(BINS - 1));
      unsigned int b1 = min((unsigned int)(d1 * (float)BINS), (unsigned int)(BINS - 1));
      atomicAdd(&sh[b0],        m0 ? 0x10000u : 1u);
      atomicAdd(&sh[BINS + b1], m0 ? 1u : 0x10000u);
    }
  }
  __syncthreads();

  // flush: plain vectorized stores to this block's private slot
  uint4* __restrict__ dst =
      (uint4*)(g_part + ((size_t)(n * BPS + b) * NC) * BINS);
  const uint4* __restrict__ src = (const uint4*)sh;
#pragma unroll
  for (int i = tid; i < (2 * BINS) / 4; i += HT) dst[i] = src[i];

  // npred block reduce + 2 global atomics
  int lane = tid & 31, w = tid >> 5;
#pragma unroll
  for (int off = 16; off; off >>= 1) {
    c0 += __shfl_down_sync(0xffffffffu, c0, off);
    c1 += __shfl_down_sync(0xffffffffu, c1, off);
  }
  __shared__ int s0[NW], s1[NW];
  if (lane == 0) { s0[w] = c0; s1[w] = c1; }
  __syncthreads();
  if (tid == 0) {
    int a = 0, bb = 0;
#pragma unroll
    for (int i = 0; i < NW; i++) { a += s0[i]; bb += s1[i]; }
    atomicAdd(&g_npred[n], a);
    atomicAdd(&g_npred[NB + n], bb);
  }
}

// ---------------------------------------------------------------- scan + finalize
// One block per row. Sums BPS partial hists, block-scans, Lovász walk.
// Last-finishing block does the deterministic final reduction with 64 lanes.
__global__ void __launch_bounds__(ST) k_scan(const float* __restrict__ cw,
                                             const float* __restrict__ tw,
                                             float* __restrict__ out) {
  const int r    = blockIdx.x;        // row = cc*NB + n
  const int cc   = r >> 5;
  const int n    = r & 31;
  const int t    = threadIdx.x;
  const int lane = t & 31;
  const int w    = t >> 5;

  // thread t owns SEG bins [g, g+SEG); thread 0 owns the HIGHEST bins
  const int g = BINS - SEG - t * SEG;

  // fully unrolled: 16 independent LDG.64 front-batched (MLP 16)
  unsigned int h1[SEG], htot[SEG];
#pragma unroll
  for (int j = 0; j < SEG; j++) { h1[j] = 0u; htot[j] = 0u; }

#pragma unroll
  for (int b = 0; b < BPS; b++) {
    uint2 v = *(const uint2*)(g_part + ((size_t)(n * BPS + b) * NC + cc) * BINS + g);
    unsigned int vv[2] = {v.x, v.y};
#pragma unroll
    for (int j = 0; j < SEG; j++) {
      unsigned int one = vv[j] >> 16;
      h1[j]   += one;
      htot[j] += one + (vv[j] & 0xffffu);
    }
  }

  // segment sums
  unsigned int s1 = 0, st = 0;
#pragma unroll
  for (int j = 0; j < SEG; j++) { s1 += h1[j]; st += htot[j]; }

  // inclusive block scan over packed (s1|st) via warp shuffles
  __shared__ unsigned long long swarp[SNW];
  unsigned long long mine = ((unsigned long long)s1 << 32) | (unsigned long long)st;
  unsigned long long inc = mine;
#pragma unroll
  for (int off = 1; off < 32; off <<= 1) {
    unsigned long long u = __shfl_up_sync(0xffffffffu, inc, off);
    if (lane >= off) inc += u;
  }
  if (lane == 31) swarp[w] = inc;
  __syncthreads();
  if (w == 0) {
    unsigned long long v = (lane < SNW) ? swarp[lane] : 0ull;
#pragma unroll
    for (int off = 1; off < SNW; off <<= 1) {
      unsigned long long u = __shfl_up_sync(0xffffffffu, v, off);
      if (lane >= off) v += u;
    }
    if (lane < SNW) swarp[lane] = v;
  }
  __syncthreads();
  unsigned long long woff = (w == 0) ? 0ull : swarp[w - 1];
  unsigned long long tot  = swarp[SNW - 1];
  unsigned long long excl = woff + inc - mine;

  const unsigned int gts = (unsigned int)(tot >> 32);
  unsigned int K1 = (unsigned int)(excl >> 32);
  unsigned int K  = (unsigned int)(excl & 0xffffffffull);

  float iou_prev = (K == 0)
      ? 0.0f
      : 1.0f - __fdividef((float)(gts - K1), (float)(gts + K - K1));

  // walk the segment high->low:  acc += d_bin * (iou - iou_prev)
  float acc = 0.0f;
#pragma unroll
  for (int j = SEG - 1; j >= 0; j--) {
    if (htot[j]) {
      K1 += h1[j];
      K  += htot[j];
      float iou = 1.0f - __fdividef((float)(gts - K1), (float)(gts + K - K1));
      float d   = ((float)(g + j) + 0.5f) * (1.0f / (float)BINS);
      acc += d * (iou - iou_prev);
      iou_prev = iou;
    }
  }

  // block reduce acc (fixed tree -> deterministic)
  __shared__ float sred[SNW];
#pragma unroll
  for (int off = 16; off; off >>= 1)
    acc += __shfl_down_sync(0xffffffffu, acc, off);
  if (lane == 0) sred[w] = acc;
  __syncthreads();

  __shared__ int slast;
  if (t == 0) {
    float per = 0.0f;
#pragma unroll
    for (int i = 0; i < SNW; i++) per += sred[i];
    int   np    = g_npred[r];
    float cwv   = cw[cc];
    bool  empty = (gts == 0) && (np == 0);
    bool  valid = (cwv != 0.0f) && !empty;
    g_wrow[r]  = valid ? per * tw[n] * cwv : 0.0f;
    g_valid[r] = valid ? 1u : 0u;
    g_npred[r] = 0;                      // reset for next replay
    __threadfence();
    int old = atomicAdd(&g_done, 1);
    slast = (old == ROWS - 1);
  }
  __syncthreads();

  // last-finishing block: parallel deterministic final reduction (64 lanes)
  if (slast) {
    __threadfence();
    float Wv = 0.0f, Vv = 0.0f;
    if (t < ROWS) {
      Wv = __ldcg(&g_wrow[t]);
      Vv = (float)__ldcg(&g_valid[t]);
    }
#pragma unroll
    for (int off = 16; off; off >>= 1) {
      Wv += __shfl_down_sync(0xffffffffu, Wv, off);
      Vv += __shfl_down_sync(0xffffffffu, Vv, off);
    }
    __shared__ float fw[2], fv[2];
    if (lane == 0 && w < 2) { fw[w] = Wv; fv[w] = Vv; }
    __syncthreads();
    if (t == 0) {
      out[0] = (fw[0] + fw[1]) / (float)NB / (fv[0] + fv[1]);
      g_done = 0;                        // reset for next replay
    }
  }
}

// ---------------------------------------------------------------- launch
extern "C" void kernel_launch(void* const* d_in, const int* in_sizes, int n_in,
                              void* d_out, int out_size) {
  const float* x   = (const float*)d_in[0];
  const void*  tgt = d_in[1];
  const float* cw  = (const float*)d_in[2];
  const float* tw  = (const float*)d_in[3];
  float* out = (float*)d_out;

  dim3 grid(BPS, NB);
  k_hist<<<grid, HT>>>(x, tgt);
  k_scan<<<ROWS, ST>>>(cw, tw, out);
}

// round 7
// speedup vs baseline: 1.4118x; 1.0566x over previous
#include <cuda_runtime.h>

#define NB    32
#define NC    2
#define PP    262144             // H*W
#define BINS  2048
#define ROWS  (NC * NB)          // 64 rows, row = cc*NB + n
#define BPS   8                  // blocks per sample -> 256 blocks
#define HT    1024               // hist threads per block
#define NW    (HT / 32)
#define PXB   (PP / BPS)         // 32768 pixels per block
#define ITERS (PXB / (HT * 4))   // 8 iterations of 4 pixels
#define ST    512                // scan threads
#define SEG   (BINS / ST)        // 4 bins per scan thread
#define SNW   (ST / 32)

// Scratch (static device globals, zero-initialized at load; reset each call)
__device__ unsigned int g_part[(size_t)NB * BPS * NC * BINS]; // per-block partial hists (overwritten)
__device__ int          g_npred[ROWS];
__device__ int          g_done;
__device__ float        g_wrow[ROWS];
__device__ unsigned int g_valid[ROWS];

// ---------------------------------------------------------------- histogram
// grid = (BPS, NB). Private smem hist, plain STG flush to g_part (no atomics).
__global__ void __launch_bounds__(HT) k_hist(const float* __restrict__ x,
                                             const void*  __restrict__ tgt) {
  __shared__ unsigned int sh[2 * BINS];   // 16 KB: [0,BINS)=c0, [BINS,2B)=c1
  const int n   = blockIdx.y;
  const int b   = blockIdx.x;
  const int tid = threadIdx.x;

  for (int i = tid; i < 2 * BINS; i += HT) sh[i] = 0u;

  // Detect targets dtype: if int32, odd 32-bit words carry real data -> some
  // nonzero. If int64 (values 0/1), odd words are all zero. Doubles as barrier.
  const int* t32 = (const int*)tgt;
  int probe = t32[2 * tid + 1];
  bool is32 = __syncthreads_or(probe != 0);

  const int base = b * PXB;
  int c0 = 0, c1 = 0;
#pragma unroll 4
  for (int it = 0; it < ITERS; it++) {
    const int p = base + (it * HT + tid) * 4;

    long long tv[4];
    if (is32) {
      int4 q = *(const int4*)(t32 + (size_t)n * PP + p);
      tv[0] = q.x; tv[1] = q.y; tv[2] = q.z; tv[3] = q.w;
    } else {
      longlong4 q = *(const longlong4*)((const long long*)tgt + (size_t)n * PP + p);
      tv[0] = q.x; tv[1] = q.y; tv[2] = q.z; tv[3] = q.w;
    }
    float4 v0 = *(const float4*)(x + ((size_t)n * NC + 0) * PP + p);
    float4 v1 = *(const float4*)(x + ((size_t)n * NC + 1) * PP + p);
    float xs0[4] = {v0.x, v0.y, v0.z, v0.w};
    float xs1[4] = {v1.x, v1.y, v1.z, v1.w};

#pragma unroll
    for (int k = 0; k < 4; k++) {
      bool  m0 = (tv[k] == 0);            // class-0 mask; class-1 mask = !m0
      float a0 = xs0[k], a1 = xs1[k];
      c0 += (a0 > 0.25f);
      c1 += (a1 > 0.25f);
      float d0 = m0 ? (1.0f - a0) : a0;   // |mask - x|
      float d1 = m0 ? a1 : (1.0f - a1);
      unsigned int b0 = min((unsigned int)(d0 * (float)BINS), (unsigned int)(BINS - 1));
      unsigned int b1 = min((unsigned int)(d1 * (float)BINS), (unsigned int)(BINS - 1));
      atomicAdd(&sh[b0],        m0 ? 0x10000u : 1u);
      atomicAdd(&sh[BINS + b1], m0 ? 1u : 0x10000u);
    }
  }
  __syncthreads();

  // flush: plain vectorized stores to this block's private slot
  uint4* __restrict__ dst =
      (uint4*)(g_part + ((size_t)(n * BPS + b) * NC) * BINS);
  const uint4* __restrict__ src = (const uint4*)sh;
#pragma unroll
  for (int i = tid; i < (2 * BINS) / 4; i += HT) dst[i] = src[i];

  // npred block reduce + 2 global atomics
  int lane = tid & 31, w = tid >> 5;
#pragma unroll
  for (int off = 16; off; off >>= 1) {
    c0 += __shfl_down_sync(0xffffffffu, c0, off);
    c1 += __shfl_down_sync(0xffffffffu, c1, off);
  }
  __shared__ int s0[NW], s1[NW];
  if (lane == 0) { s0[w] = c0; s1[w] = c1; }
  __syncthreads();
  if (tid == 0) {
    int a = 0, bb = 0;
#pragma unroll
    for (int i = 0; i < NW; i++) { a += s0[i]; bb += s1[i]; }
    atomicAdd(&g_npred[n], a);
    atomicAdd(&g_npred[NB + n], bb);
  }
}

// ---------------------------------------------------------------- scan + finalize
// One block per row. Sums BPS partial hists (LDG.128), block-scans, Lovász walk.
// Last-finishing block does the deterministic final reduction with 64 lanes.
__global__ void __launch_bounds__(ST) k_scan(const float* __restrict__ cw,
                                             const float* __restrict__ tw,
                                             float* __restrict__ out) {
  const int r    = blockIdx.x;        // row = cc*NB + n
  const int cc   = r >> 5;
  const int n    = r & 31;
  const int t    = threadIdx.x;
  const int lane = t & 31;
  const int w    = t >> 5;

  // thread t owns SEG bins [g, g+SEG); thread 0 owns the HIGHEST bins
  const int g = BINS - SEG - t * SEG;

  // fully unrolled: 8 independent LDG.128 front-batched (MLP 8)
  unsigned int h1[SEG], htot[SEG];
#pragma unroll
  for (int j = 0; j < SEG; j++) { h1[j] = 0u; htot[j] = 0u; }

#pragma unroll
  for (int b = 0; b < BPS; b++) {
    uint4 v = *(const uint4*)(g_part + ((size_t)(n * BPS + b) * NC + cc) * BINS + g);
    unsigned int vv[4] = {v.x, v.y, v.z, v.w};
#pragma unroll
    for (int j = 0; j < SEG; j++) {
      unsigned int one = vv[j] >> 16;
      h1[j]   += one;
      htot[j] += one + (vv[j] & 0xffffu);
    }
  }

  // segment sums
  unsigned int s1 = 0, st = 0;
#pragma unroll
  for (int j = 0; j < SEG; j++) { s1 += h1[j]; st += htot[j]; }

  // inclusive block scan over packed (s1|st) via warp shuffles
  __shared__ unsigned long long swarp[SNW];
  unsigned long long mine = ((unsigned long long)s1 << 32) | (unsigned long long)st;
  unsigned long long inc = mine;
#pragma unroll
  for (int off = 1; off < 32; off <<= 1) {
    unsigned long long u = __shfl_up_sync(0xffffffffu, inc, off);
    if (lane >= off) inc += u;
  }
  if (lane == 31) swarp[w] = inc;
  __syncthreads();
  if (w == 0) {
    unsigned long long v = (lane < SNW) ? swarp[lane] : 0ull;
#pragma unroll
    for (int off = 1; off < SNW; off <<= 1) {
      unsigned long long u = __shfl_up_sync(0xffffffffu, v, off);
      if (lane >= off) v += u;
    }
    if (lane < SNW) swarp[lane] = v;
  }
  __syncthreads();
  unsigned long long woff = (w == 0) ? 0ull : swarp[w - 1];
  unsigned long long tot  = swarp[SNW - 1];
  unsigned long long excl = woff + inc - mine;

  const unsigned int gts = (unsigned int)(tot >> 32);
  unsigned int K1 = (unsigned int)(excl >> 32);
  unsigned int K  = (unsigned int)(excl & 0xffffffffull);

  float iou_prev = (K == 0)
      ? 0.0f
      : 1.0f - __fdividef((float)(gts - K1), (float)(gts + K - K1));

  // walk the segment high->low:  acc += d_bin * (iou - iou_prev)
  float acc = 0.0f;
#pragma unroll
  for (int j = SEG - 1; j >= 0; j--) {
    if (htot[j]) {
      K1 += h1[j];
      K  += htot[j];
      float iou = 1.0f - __fdividef((float)(gts - K1), (float)(gts + K - K1));
      float d   = ((float)(g + j) + 0.5f) * (1.0f / (float)BINS);
      acc += d * (iou - iou_prev);
      iou_prev = iou;
    }
  }

  // block reduce acc (fixed tree -> deterministic)
  __shared__ float sred[SNW];
#pragma unroll
  for (int off = 16; off; off >>= 1)
    acc += __shfl_down_sync(0xffffffffu, acc, off);
  if (lane == 0) sred[w] = acc;
  __syncthreads();

  __shared__ int slast;
  if (t == 0) {
    float per = 0.0f;
#pragma unroll
    for (int i = 0; i < SNW; i++) per += sred[i];
    int   np    = g_npred[r];
    float cwv   = cw[cc];
    bool  empty = (gts == 0) && (np == 0);
    bool  valid = (cwv != 0.0f) && !empty;
    g_wrow[r]  = valid ? per * tw[n] * cwv : 0.0f;
    g_valid[r] = valid ? 1u : 0u;
    g_npred[r] = 0;                      // reset for next replay
    __threadfence();
    int old = atomicAdd(&g_done, 1);
    slast = (old == ROWS - 1);
  }
  __syncthreads();

  // last-finishing block: parallel deterministic final reduction (64 lanes)
  if (slast) {
    __threadfence();
    float Wv = 0.0f, Vv = 0.0f;
    if (t < ROWS) {
      Wv = __ldcg(&g_wrow[t]);
      Vv = (float)__ldcg(&g_valid[t]);
    }
#pragma unroll
    for (int off = 16; off; off >>= 1) {
      Wv += __shfl_down_sync(0xffffffffu, Wv, off);
      Vv += __shfl_down_sync(0xffffffffu, Vv, off);
    }
    __shared__ float fw[2], fv[2];
    if (lane == 0 && w < 2) { fw[w] = Wv; fv[w] = Vv; }
    __syncthreads();
    if (t == 0) {
      out[0] = (fw[0] + fw[1]) / (float)NB / (fv[0] + fv[1]);
      g_done = 0;                        // reset for next replay
    }
  }
}

// ---------------------------------------------------------------- launch
extern "C" void kernel_launch(void* const* d_in, const int* in_sizes, int n_in,
                              void* d_out, int out_size) {
  const float* x   = (const float*)d_in[0];
  const void*  tgt = d_in[1];
  const float* cw  = (const float*)d_in[2];
  const float* tw  = (const float*)d_in[3];
  float* out = (float*)d_out;

  dim3 grid(BPS, NB);
  k_hist<<<grid, HT>>>(x, tgt);
  k_scan<<<ROWS, ST>>>(cw, tw, out);
}